// round 1
// baseline (speedup 1.0000x reference)
#include <cuda_runtime.h>
#include <math.h>

#define BB 8
#define TT 1024
#define EE 1024
#define HH 16
#define DD 64

// Scratch (allocation-free rule: __device__ globals). 32 MB each.
__device__ float g_q2[BB*HH*TT*DD];
__device__ float g_v2[BB*HH*TT*DD];
__device__ float g_nw[BB*HH*TT*DD];

// ---------------------------------------------------------------------------
// Kernel 1: per-head projections  q2 = src @ W_q[h],  v2 = tgt @ W_v[h]
// out[b,h,t,e] = sum_d in[b,t,h*64+d] * W[h,d,e]
// grid: (t_tile=16, h=16, z=16 where b=z&7, sel=z>>3), 256 threads
// ---------------------------------------------------------------------------
__global__ __launch_bounds__(256) void proj_kernel(const float* __restrict__ src,
                                                   const float* __restrict__ tgt,
                                                   const float* __restrict__ Wq,
                                                   const float* __restrict__ Wv) {
    __shared__ float Is[64*64];
    __shared__ float Ws[64*64];
    int tt = blockIdx.x, h = blockIdx.y, z = blockIdx.z;
    int b = z & 7, sel = z >> 3;
    const float* in = sel ? tgt : src;
    const float* W  = (sel ? Wv : Wq) + h * 4096;
    float* outp = (sel ? g_v2 : g_q2) + ((size_t)(b*HH + h)*TT + tt*64)*DD;
    int tid = threadIdx.x;

    for (int i = tid; i < 1024; i += 256) ((float4*)Ws)[i] = ((const float4*)W)[i];
    for (int i = tid; i < 1024; i += 256) {
        int r = i >> 4, c4 = i & 15;
        ((float4*)Is)[i] = *(const float4*)(in + ((size_t)b*TT + tt*64 + r)*EE + h*DD + c4*4);
    }
    __syncthreads();

    int tx = tid & 15, ty = tid >> 4;
    int row0 = ty*4, col0 = tx*4;
    float acc[4][4];
    #pragma unroll
    for (int i=0;i<4;i++)
        #pragma unroll
        for (int j=0;j<4;j++) acc[i][j]=0.f;

    #pragma unroll 4
    for (int k4 = 0; k4 < 16; k4++) {
        float a[4][4];
        #pragma unroll
        for (int i=0;i<4;i++) *(float4*)a[i] = *(const float4*)&Is[(row0+i)*64 + k4*4];
        #pragma unroll
        for (int kk=0;kk<4;kk++) {
            float bv[4];
            *(float4*)bv = *(const float4*)&Ws[(k4*4+kk)*64 + col0];
            #pragma unroll
            for (int i=0;i<4;i++)
                #pragma unroll
                for (int j=0;j<4;j++) acc[i][j] += a[i][kk]*bv[j];
        }
    }
    #pragma unroll
    for (int i=0;i<4;i++)
        *(float4*)(outp + (row0+i)*64 + col0) = *(float4*)acc[i];
}

// ---------------------------------------------------------------------------
// Kernel 2: RNN recurrence. One block per (b,h) sequence, 64 threads.
// h1 = tanh(W_ih @ k0 + b_ih + b_hh);  h_{n+1} = tanh((W_ih+W_hh) @ h_n + b)
// Thread e holds row e of M in registers; state double-buffered in shared.
// ---------------------------------------------------------------------------
__global__ __launch_bounds__(64) void rnn_kernel(const float* __restrict__ tgt,
                                                 const float* __restrict__ Wih,
                                                 const float* __restrict__ Whh,
                                                 const float* __restrict__ bih,
                                                 const float* __restrict__ bhh) {
    __shared__ __align__(16) float hs[2][64];
    __shared__ __align__(16) float k0s[64];
    int bh = blockIdx.x;
    int b = bh >> 4, h = bh & 15;
    int e = threadIdx.x;

    k0s[e] = tgt[(size_t)b*TT*EE + h*DD + e];
    float c = bih[h*DD + e] + bhh[h*DD + e];

    float Wr[64];
    const float* wi = Wih + (size_t)(h*DD + e)*DD;
    #pragma unroll
    for (int d4 = 0; d4 < 16; d4++) *(float4*)&Wr[d4*4] = *(const float4*)&wi[d4*4];
    __syncthreads();

    float a0=0.f,a1=0.f,a2=0.f,a3=0.f;
    #pragma unroll
    for (int d4 = 0; d4 < 16; d4++) {
        float hv[4]; *(float4*)hv = *(const float4*)&k0s[d4*4];
        a0 += Wr[d4*4+0]*hv[0]; a1 += Wr[d4*4+1]*hv[1];
        a2 += Wr[d4*4+2]*hv[2]; a3 += Wr[d4*4+3]*hv[3];
    }
    float hv1 = tanhf(a0+a1+a2+a3 + c);
    float* nwp = g_nw + (size_t)bh*TT*DD;
    hs[0][e] = hv1;
    nwp[e] = hv1;

    const float* wh = Whh + (size_t)(h*DD + e)*DD;
    #pragma unroll
    for (int d4 = 0; d4 < 16; d4++) {
        float t4[4]; *(float4*)t4 = *(const float4*)&wh[d4*4];
        Wr[d4*4+0] += t4[0]; Wr[d4*4+1] += t4[1];
        Wr[d4*4+2] += t4[2]; Wr[d4*4+3] += t4[3];
    }
    __syncthreads();

    int cur = 0;
    for (int t = 1; t < TT; t++) {
        float b0=0.f,b1=0.f,b2=0.f,b3=0.f;
        const float* hc = hs[cur];
        #pragma unroll
        for (int d4 = 0; d4 < 16; d4++) {
            float hv[4]; *(float4*)hv = *(const float4*)&hc[d4*4];
            b0 += Wr[d4*4+0]*hv[0]; b1 += Wr[d4*4+1]*hv[1];
            b2 += Wr[d4*4+2]*hv[2]; b3 += Wr[d4*4+3]*hv[3];
        }
        float hn = tanhf(b0+b1+b2+b3 + c);
        hs[cur^1][e] = hn;
        nwp[(size_t)t*DD + e] = hn;
        cur ^= 1;
        __syncthreads();
    }
}

// ---------------------------------------------------------------------------
// Kernel 3: flash attention (64-row q tiles) + fused W_o epilogue.
// logits = (q . nw) / 256; online softmax; O = P@V; out = O @ W_o[h].
// grid: (qt=16, h=16, b=8), 256 threads, 48 KB static shared.
// K tile XOR-swizzled (mask = row & 28) to keep float4 row reads ~2-way.
// ---------------------------------------------------------------------------
__global__ __launch_bounds__(256) void attn_kernel(const float* __restrict__ Wo,
                                                   float* __restrict__ out) {
    __shared__ float Qs[64*64];
    __shared__ float KPs[64*64];
    __shared__ float Vs[64*64];
    int qt = blockIdx.x, h = blockIdx.y, b = blockIdx.z;
    int bh = b*HH + h;
    int tid = threadIdx.x;
    int tx = tid & 15, ty = tid >> 4;
    int row0 = ty*4, col0 = tx*4;

    const float* qsrc = g_q2 + ((size_t)bh*TT + qt*64)*DD;
    for (int i = tid; i < 1024; i += 256) ((float4*)Qs)[i] = ((const float4*)qsrc)[i];

    const float* ksrc = g_nw + (size_t)bh*TT*DD;
    const float* vsrc = g_v2 + (size_t)bh*TT*DD;

    float m_i[4], l_i[4], o[4][4];
    #pragma unroll
    for (int i=0;i<4;i++) {
        m_i[i] = -1e30f; l_i[i] = 0.f;
        #pragma unroll
        for (int j=0;j<4;j++) o[i][j]=0.f;
    }
    int xm[4];
    #pragma unroll
    for (int j=0;j<4;j++) xm[j] = (col0+j) & 28;
    const float scale = 1.0f/256.0f;

    for (int kt = 0; kt < 16; kt++) {
        __syncthreads();   // prior-iter reads of KPs/Vs done (and Q load on iter 0)
        const float4* k4p = (const float4*)(ksrc + kt*4096);
        for (int i = tid; i < 1024; i += 256) {
            int r = i >> 4, c4 = i & 15;
            float4 val = k4p[i];
            *(float4*)&KPs[r*64 + ((c4*4) ^ (r & 28))] = val;
        }
        const float4* v4p = (const float4*)(vsrc + kt*4096);
        for (int i = tid; i < 1024; i += 256) ((float4*)Vs)[i] = v4p[i];
        __syncthreads();

        // S = Q @ K^T
        float s[4][4];
        #pragma unroll
        for (int i=0;i<4;i++)
            #pragma unroll
            for (int j=0;j<4;j++) s[i][j]=0.f;
        #pragma unroll 4
        for (int d4 = 0; d4 < 16; d4++) {
            float qv[4][4], kv[4][4];
            #pragma unroll
            for (int i=0;i<4;i++) *(float4*)qv[i] = *(const float4*)&Qs[(row0+i)*64 + d4*4];
            #pragma unroll
            for (int j=0;j<4;j++) *(float4*)kv[j] = *(const float4*)&KPs[(col0+j)*64 + ((d4*4) ^ xm[j])];
            #pragma unroll
            for (int dd=0;dd<4;dd++)
                #pragma unroll
                for (int i=0;i<4;i++)
                    #pragma unroll
                    for (int j=0;j<4;j++) s[i][j] += qv[i][dd]*kv[j][dd];
        }

        // online softmax (row stats replicated across the 16 lanes of a row group)
        float fac[4];
        #pragma unroll
        for (int i=0;i<4;i++) {
            #pragma unroll
            for (int j=0;j<4;j++) s[i][j] *= scale;
            float mx = fmaxf(fmaxf(s[i][0],s[i][1]), fmaxf(s[i][2],s[i][3]));
            #pragma unroll
            for (int off=1; off<16; off<<=1) mx = fmaxf(mx, __shfl_xor_sync(0xffffffffu, mx, off));
            float mnew = fmaxf(m_i[i], mx);
            fac[i] = __expf(m_i[i] - mnew);
            m_i[i] = mnew;
            float ls = 0.f;
            #pragma unroll
            for (int j=0;j<4;j++) { s[i][j] = __expf(s[i][j]-mnew); ls += s[i][j]; }
            #pragma unroll
            for (int off=1; off<16; off<<=1) ls += __shfl_xor_sync(0xffffffffu, ls, off);
            l_i[i] = l_i[i]*fac[i] + ls;
        }
        __syncthreads();   // all K reads done before P overwrites the buffer
        #pragma unroll
        for (int i=0;i<4;i++)
            *(float4*)&KPs[(row0+i)*64 + col0] = *(float4*)s[i];
        __syncthreads();

        // O = O*fac + P @ V
        #pragma unroll
        for (int i=0;i<4;i++)
            #pragma unroll
            for (int j=0;j<4;j++) o[i][j] *= fac[i];
        #pragma unroll 4
        for (int k4=0;k4<16;k4++) {
            float pv[4][4];
            #pragma unroll
            for (int i=0;i<4;i++) *(float4*)pv[i] = *(const float4*)&KPs[(row0+i)*64 + k4*4];
            #pragma unroll
            for (int kk=0;kk<4;kk++) {
                float vv[4];
                *(float4*)vv = *(const float4*)&Vs[(k4*4+kk)*64 + col0];
                #pragma unroll
                for (int i=0;i<4;i++)
                    #pragma unroll
                    for (int j=0;j<4;j++) o[i][j] += pv[i][kk]*vv[j];
            }
        }
    }

    // epilogue: normalize, then fused O @ W_o[h]
    __syncthreads();
    #pragma unroll
    for (int i=0;i<4;i++) {
        float inv = 1.0f/l_i[i];
        float tmp[4];
        #pragma unroll
        for (int j=0;j<4;j++) tmp[j] = o[i][j]*inv;
        *(float4*)&KPs[(row0+i)*64 + col0] = *(float4*)tmp;
    }
    const float4* w4 = (const float4*)(Wo + h*4096);
    for (int i = tid; i < 1024; i += 256) ((float4*)Vs)[i] = w4[i];
    __syncthreads();

    float r2[4][4];
    #pragma unroll
    for (int i=0;i<4;i++)
        #pragma unroll
        for (int j=0;j<4;j++) r2[i][j]=0.f;
    #pragma unroll 4
    for (int k4=0;k4<16;k4++) {
        float av[4][4];
        #pragma unroll
        for (int i=0;i<4;i++) *(float4*)av[i] = *(const float4*)&KPs[(row0+i)*64 + k4*4];
        #pragma unroll
        for (int kk=0;kk<4;kk++) {
            float bv[4];
            *(float4*)bv = *(const float4*)&Vs[(k4*4+kk)*64 + col0];
            #pragma unroll
            for (int i=0;i<4;i++)
                #pragma unroll
                for (int j=0;j<4;j++) r2[i][j] += av[i][kk]*bv[j];
        }
    }
    #pragma unroll
    for (int i=0;i<4;i++)
        *(float4*)(out + ((size_t)b*TT + qt*64 + row0 + i)*EE + h*DD + col0) = *(float4*)r2[i];
}

// ---------------------------------------------------------------------------
extern "C" void kernel_launch(void* const* d_in, const int* in_sizes, int n_in,
                              void* d_out, int out_size) {
    const float* src = (const float*)d_in[0];
    const float* tgt = (const float*)d_in[1];
    const float* Wq  = (const float*)d_in[2];
    const float* Wv  = (const float*)d_in[3];
    const float* Wo  = (const float*)d_in[4];
    const float* Wih = (const float*)d_in[5];
    const float* Whh = (const float*)d_in[6];
    const float* bih = (const float*)d_in[7];
    const float* bhh = (const float*)d_in[8];
    float* out = (float*)d_out;

    proj_kernel<<<dim3(16,16,16), 256>>>(src, tgt, Wq, Wv);
    rnn_kernel<<<128, 64>>>(tgt, Wih, Whh, bih, bhh);
    attn_kernel<<<dim3(16,16,8), 256>>>(Wo, out);
}